// round 1
// baseline (speedup 1.0000x reference)
#include <cuda_runtime.h>
#include <cstdint>

typedef unsigned long long ULL;

#define NTOK 1024
#define CQ   768
#define CZ   128
#define NH   16
#define HD   48
#define HDQ  768   // NH*HD
#define QSCALE 0.14433756729740643f  // 1/sqrt(48)

// ---------------- f32x2 packed helpers ----------------
__device__ __forceinline__ ULL fma2(ULL a, ULL b, ULL c) {
    ULL d; asm("fma.rn.f32x2 %0, %1, %2, %3;" : "=l"(d) : "l"(a), "l"(b), "l"(c)); return d;
}
__device__ __forceinline__ ULL add2(ULL a, ULL b) {
    ULL d; asm("add.rn.f32x2 %0, %1, %2;" : "=l"(d) : "l"(a), "l"(b)); return d;
}
__device__ __forceinline__ ULL pack2(float lo, float hi) {
    ULL d; asm("mov.b64 %0, {%1, %2};" : "=l"(d) : "f"(lo), "f"(hi)); return d;
}
__device__ __forceinline__ float lo2(ULL u){ return __uint_as_float((unsigned)u); }
__device__ __forceinline__ float hi2(ULL u){ return __uint_as_float((unsigned)(u >> 32)); }

// ---------------- scratch (static device globals; no allocation) ----------------
__device__ float g_an[NTOK * CQ];                       // LN(a)
__device__ float g_scores[(size_t)NH * NTOK * NTOK];    // pair_bias -> scores -> softmax P
__device__ float g_q[NH * NTOK * HD];                   // [h][n][d]
__device__ float g_kT[NH * HD * NTOK];                  // [h][d][n]
__device__ float g_v[NH * NTOK * HD];                   // [h][n][d]
__device__ float g_gate[NTOK * HDQ];                    // sigmoid(an@w_g + b_g)
__device__ float g_og[NTOK * HDQ];                      // gated attention output

// ---------------- LayerNorm of a ----------------
__global__ void k_ln_a(const float* __restrict__ a, const float* __restrict__ g,
                       const float* __restrict__ b) {
    int row = blockIdx.x, tid = threadIdx.x;
    const float* x = a + (size_t)row * CQ;
    float v0 = x[tid], v1 = x[tid + 256], v2 = x[tid + 512];
    float s = v0 + v1 + v2;
    float ss = v0*v0 + v1*v1 + v2*v2;
    __shared__ float sm[8], sm2[8];
    #pragma unroll
    for (int o = 16; o; o >>= 1) {
        s  += __shfl_xor_sync(0xffffffffu, s, o);
        ss += __shfl_xor_sync(0xffffffffu, ss, o);
    }
    if ((tid & 31) == 0) { sm[tid >> 5] = s; sm2[tid >> 5] = ss; }
    __syncthreads();
    if (tid == 0) {
        float S = 0, SS = 0;
        for (int i = 0; i < 8; i++) { S += sm[i]; SS += sm2[i]; }
        float mu = S * (1.0f / CQ);
        float var = SS * (1.0f / CQ) - mu * mu;
        sm[0] = mu; sm2[0] = rsqrtf(var + 1e-5f);
    }
    __syncthreads();
    float mu = sm[0], rstd = sm2[0];
    float* o = g_an + (size_t)row * CQ;
    o[tid]       = (v0 - mu) * rstd * g[tid]       + b[tid];
    o[tid + 256] = (v1 - mu) * rstd * g[tid + 256] + b[tid + 256];
    o[tid + 512] = (v2 - mu) * rstd * g[tid + 512] + b[tid + 512];
}

// ---------------- pair bias: LN(z) @ w_z, fused, written into g_scores[h][i][j] ----------------
// bias[h] = rstd*(dot_raw[h] - mu*colsum[h]) + cb[h]
//   wg[c][h] = g_z[c]*w_z[c][h]; colsum[h] = sum_c wg; cb[h] = sum_c b_z[c]*w_z[c][h]
__global__ void k_pair_bias(const float* __restrict__ z, const float* __restrict__ gz,
                            const float* __restrict__ bz, const float* __restrict__ wz) {
    __shared__ float wps[CZ * NH];      // [cp][h][2]: wps[(c>>1)*32 + h*2 + (c&1)]
    __shared__ float cs_cb[32];         // colsum[16], cb[16]
    __shared__ float zt[64 * CZ];       // 64 rows x 128 ch, chunk-rotated
    __shared__ float outs[64 * NH];     // transpose staging for output

    int tid = threadIdx.x;  // 64 threads

    // weight prep
    for (int i = tid; i < CZ * NH; i += 64) {
        int c = i >> 4, h = i & 15;
        float wg = gz[c] * wz[c * NH + h];
        wps[(c >> 1) * 32 + h * 2 + (c & 1)] = wg;
    }
    __syncthreads();
    if (tid < 16) {
        float cs = 0.f, cb = 0.f;
        for (int c = 0; c < CZ; c++) {
            cs += wps[(c >> 1) * 32 + tid * 2 + (c & 1)];
            cb += bz[c] * wz[c * NH + tid];
        }
        cs_cb[tid] = cs; cs_cb[16 + tid] = cb;
    }
    __syncthreads();

    const int NTILES = NTOK * NTOK / 64;  // 16384
    for (int tile = blockIdx.x; tile < NTILES; tile += gridDim.x) {
        // stage 64 rows (coalesced), rotated chunk layout: row r chunk c -> phys (c+r)&31
        const float4* zg = (const float4*)(z + (size_t)tile * 64 * CZ);
        for (int i = tid; i < 64 * 32; i += 64) {
            int r = i >> 5, cc = i & 31;
            float4 v = zg[i];
            int pc = (cc + r) & 31;
            *(float4*)&zt[r * CZ + pc * 4] = v;
        }
        __syncthreads();

        int row = tid;
        ULL acc[NH];
        #pragma unroll
        for (int h = 0; h < NH; h++) acc[h] = 0ULL;
        ULL sum2 = 0ULL, ss2 = 0ULL;

        #pragma unroll 4
        for (int j = 0; j < 32; j++) {
            int pc = (j + row) & 31;
            float4 zv = *(const float4*)&zt[row * CZ + pc * 4];
            ULL z01 = ((const ULL*)&zv)[0];
            ULL z23 = ((const ULL*)&zv)[1];
            sum2 = add2(add2(sum2, z01), z23);
            ss2  = fma2(z01, z01, fma2(z23, z23, ss2));
            const float4* w0 = (const float4*)&wps[(2*j)     * 32];
            const float4* w1 = (const float4*)&wps[(2*j + 1) * 32];
            #pragma unroll
            for (int h2 = 0; h2 < 8; h2++) {
                float4 wa = w0[h2];
                float4 wb = w1[h2];
                acc[2*h2]     = fma2(z01, ((const ULL*)&wa)[0], acc[2*h2]);
                acc[2*h2 + 1] = fma2(z01, ((const ULL*)&wa)[1], acc[2*h2 + 1]);
                acc[2*h2]     = fma2(z23, ((const ULL*)&wb)[0], acc[2*h2]);
                acc[2*h2 + 1] = fma2(z23, ((const ULL*)&wb)[1], acc[2*h2 + 1]);
            }
        }
        float sum = lo2(sum2) + hi2(sum2);
        float ss  = lo2(ss2)  + hi2(ss2);
        float mu  = sum * (1.0f / CZ);
        float var = ss * (1.0f / CZ) - mu * mu;
        float rstd = rsqrtf(var + 1e-5f);
        #pragma unroll
        for (int h = 0; h < NH; h++) {
            float d = lo2(acc[h]) + hi2(acc[h]);
            outs[h * 64 + row] = rstd * (d - mu * cs_cb[h]) + cs_cb[16 + h];
        }
        __syncthreads();
        // write: g_scores[h][tile*64 + jl]
        for (int it = 0; it < 4; it++) {
            int idx = tid + it * 64;          // float4 index over 1024 floats
            int h = idx >> 4, j4 = (idx & 15) << 2;
            float4 v = *(float4*)&outs[h * 64 + j4];
            *(float4*)(g_scores + ((size_t)h << 20) + (size_t)tile * 64 + j4) = v;
        }
        __syncthreads();
    }
}

// ---------------- generic SGEMM core: C(64x64) tile, 256 threads, f32x2 packed ----------------
// A: MxK row-major (M multiple of 64, K multiple of 16), B: KxN row-major.
__device__ __forceinline__ void sgemm_core(
    const float* __restrict__ A, const float* __restrict__ B,
    int K, int ldA, int ldB, int Nvalid,
    int row0, int col0, float* sA, float* sB, ULL acc[4][2])
{
    int tid = threadIdx.x;
    int tm = (tid >> 4) << 2;
    int tn = (tid & 15) << 2;
    int ar = tid >> 2,  ak = (tid & 3) << 2;
    int bk = tid >> 4,  bn = (tid & 15) << 2;
    #pragma unroll
    for (int i = 0; i < 4; i++) { acc[i][0] = 0ULL; acc[i][1] = 0ULL; }

    for (int k0 = 0; k0 < K; k0 += 16) {
        float4 av = *(const float4*)(A + (size_t)(row0 + ar) * ldA + (k0 + ak));
        float4 bv = make_float4(0.f, 0.f, 0.f, 0.f);
        if (col0 + bn < Nvalid)
            bv = *(const float4*)(B + (size_t)(k0 + bk) * ldB + (col0 + bn));
        *(float4*)(sA + ar * 20 + ak) = av;
        *(float4*)(sB + bk * 64 + bn) = bv;
        __syncthreads();
        #pragma unroll
        for (int kk = 0; kk < 16; kk++) {
            float4 b4 = *(const float4*)(sB + kk * 64 + tn);
            ULL b01 = ((const ULL*)&b4)[0];
            ULL b23 = ((const ULL*)&b4)[1];
            #pragma unroll
            for (int i = 0; i < 4; i++) {
                float a = sA[(tm + i) * 20 + kk];
                ULL a2 = pack2(a, a);
                acc[i][0] = fma2(a2, b01, acc[i][0]);
                acc[i][1] = fma2(a2, b23, acc[i][1]);
            }
        }
        __syncthreads();
    }
}

// ---------------- QKVG projections (blockIdx.z selects output) ----------------
__global__ void k_qkvg(const float* __restrict__ wq, const float* __restrict__ wk,
                       const float* __restrict__ wv, const float* __restrict__ wg,
                       const float* __restrict__ bg) {
    __shared__ float sA[64 * 20], sB[16 * 64];
    ULL acc[4][2];
    int mode = blockIdx.z;
    const float* B = (mode == 0) ? wq : (mode == 1) ? wk : (mode == 2) ? wv : wg;
    int row0 = blockIdx.y * 64, col0 = blockIdx.x * 64;
    sgemm_core(g_an, B, CQ, CQ, HDQ, HDQ, row0, col0, sA, sB, acc);

    int tid = threadIdx.x;
    int tm = (tid >> 4) << 2, tn = (tid & 15) << 2;
    #pragma unroll
    for (int i = 0; i < 4; i++) {
        int row = row0 + tm + i;
        #pragma unroll
        for (int j = 0; j < 4; j++) {
            int col = col0 + tn + j;
            float v = (j & 1) ? hi2(acc[i][j >> 1]) : lo2(acc[i][j >> 1]);
            int h = col / HD, d = col - h * HD;
            if (mode == 0)      g_q [((size_t)h * NTOK + row) * HD + d] = v * QSCALE;
            else if (mode == 1) g_kT[((size_t)h * HD + d) * NTOK + row] = v;
            else if (mode == 2) g_v [((size_t)h * NTOK + row) * HD + d] = v;
            else                g_gate[(size_t)row * HDQ + col] = 1.f / (1.f + __expf(-(v + bg[col])));
        }
    }
}

// ---------------- scores: qk^T added in-place onto pair_bias, plus mask bias ----------------
__global__ void k_scores(const float* __restrict__ mask) {
    __shared__ float sA[64 * 20], sB[16 * 64];
    ULL acc[4][2];
    int h = blockIdx.z;
    const float* A = g_q  + (size_t)h * NTOK * HD;
    const float* B = g_kT + (size_t)h * HD * NTOK;
    int row0 = blockIdx.y * 64, col0 = blockIdx.x * 64;
    sgemm_core(A, B, HD, HD, NTOK, NTOK, row0, col0, sA, sB, acc);

    float* C = g_scores + ((size_t)h << 20);
    int tid = threadIdx.x;
    int tm = (tid >> 4) << 2, tn = (tid & 15) << 2;
    float4 mc = *(const float4*)(mask + col0 + tn);
    #pragma unroll
    for (int i = 0; i < 4; i++) {
        int row = row0 + tm + i;
        float mr = mask[row];
        float4* p = (float4*)(C + (size_t)row * NTOK + col0 + tn);
        float4 old = *p;
        float4 r;
        r.x = old.x + lo2(acc[i][0]) + 1e9f * (mr * mc.x - 1.f);
        r.y = old.y + hi2(acc[i][0]) + 1e9f * (mr * mc.y - 1.f);
        r.z = old.z + lo2(acc[i][1]) + 1e9f * (mr * mc.z - 1.f);
        r.w = old.w + hi2(acc[i][1]) + 1e9f * (mr * mc.w - 1.f);
        *p = r;
    }
}

// ---------------- row softmax over 1024, in place ----------------
__global__ void k_softmax() {
    int tid = threadIdx.x;
    float* p = g_scores + (size_t)blockIdx.x * NTOK + tid * 4;
    float4 v = *(float4*)p;
    __shared__ float red[8], red2[8];
    float m = fmaxf(fmaxf(v.x, v.y), fmaxf(v.z, v.w));
    #pragma unroll
    for (int o = 16; o; o >>= 1) m = fmaxf(m, __shfl_xor_sync(0xffffffffu, m, o));
    if ((tid & 31) == 0) red[tid >> 5] = m;
    __syncthreads();
    m = red[tid & 7];
    #pragma unroll
    for (int o = 4; o; o >>= 1) m = fmaxf(m, __shfl_xor_sync(0xffffffffu, m, o));

    v.x = __expf(v.x - m); v.y = __expf(v.y - m);
    v.z = __expf(v.z - m); v.w = __expf(v.w - m);
    float s = v.x + v.y + v.z + v.w;
    #pragma unroll
    for (int o = 16; o; o >>= 1) s += __shfl_xor_sync(0xffffffffu, s, o);
    if ((tid & 31) == 0) red2[tid >> 5] = s;
    __syncthreads();
    s = red2[tid & 7];
    #pragma unroll
    for (int o = 4; o; o >>= 1) s += __shfl_xor_sync(0xffffffffu, s, o);
    float inv = 1.f / s;
    v.x *= inv; v.y *= inv; v.z *= inv; v.w *= inv;
    *(float4*)p = v;
}

// ---------------- O = P @ V, gated, written as og[n][h*48+d] ----------------
__global__ void k_pv() {
    __shared__ float sA[64 * 20], sB[16 * 64];
    ULL acc[4][2];
    int h = blockIdx.z;
    const float* A = g_scores + ((size_t)h << 20);
    const float* B = g_v + (size_t)h * NTOK * HD;
    int row0 = blockIdx.y * 64;
    sgemm_core(A, B, NTOK, NTOK, HD, HD, row0, 0, sA, sB, acc);

    int tid = threadIdx.x;
    int tm = (tid >> 4) << 2, tn = (tid & 15) << 2;
    if (tn < HD) {
        #pragma unroll
        for (int i = 0; i < 4; i++) {
            int row = row0 + tm + i;
            #pragma unroll
            for (int j = 0; j < 4; j++) {
                int col = tn + j;
                float v = (j & 1) ? hi2(acc[i][j >> 1]) : lo2(acc[i][j >> 1]);
                size_t idx = (size_t)row * HDQ + h * HD + col;
                g_og[idx] = v * g_gate[idx];
            }
        }
    }
}

// ---------------- final projection ----------------
__global__ void k_out(const float* __restrict__ wo, const float* __restrict__ bo,
                      float* __restrict__ out) {
    __shared__ float sA[64 * 20], sB[16 * 64];
    ULL acc[4][2];
    int row0 = blockIdx.y * 64, col0 = blockIdx.x * 64;
    sgemm_core(g_og, wo, CQ, CQ, CQ, CQ, row0, col0, sA, sB, acc);

    int tid = threadIdx.x;
    int tm = (tid >> 4) << 2, tn = (tid & 15) << 2;
    float4 bv = *(const float4*)(bo + col0 + tn);
    #pragma unroll
    for (int i = 0; i < 4; i++) {
        int row = row0 + tm + i;
        float4 r;
        r.x = lo2(acc[i][0]) + bv.x;
        r.y = hi2(acc[i][0]) + bv.y;
        r.z = lo2(acc[i][1]) + bv.z;
        r.w = hi2(acc[i][1]) + bv.w;
        *(float4*)(out + (size_t)row * CQ + col0 + tn) = r;
    }
}

// ---------------- launch ----------------
extern "C" void kernel_launch(void* const* d_in, const int* in_sizes, int n_in,
                              void* d_out, int out_size) {
    const float* a    = (const float*)d_in[0];
    const float* z    = (const float*)d_in[1];
    const float* mask = (const float*)d_in[2];
    const float* ga   = (const float*)d_in[3];
    const float* ba   = (const float*)d_in[4];
    const float* gz   = (const float*)d_in[5];
    const float* bz   = (const float*)d_in[6];
    const float* wz   = (const float*)d_in[7];
    const float* wq   = (const float*)d_in[8];
    const float* wk   = (const float*)d_in[9];
    const float* wv   = (const float*)d_in[10];
    const float* wg   = (const float*)d_in[11];
    const float* bg   = (const float*)d_in[12];
    const float* wo   = (const float*)d_in[13];
    const float* bo   = (const float*)d_in[14];
    float* out = (float*)d_out;

    k_pair_bias<<<2048, 64>>>(z, gz, bz, wz);
    k_ln_a<<<1024, 256>>>(a, ga, ba);
    k_qkvg<<<dim3(12, 16, 4), 256>>>(wq, wk, wv, wg, bg);
    k_scores<<<dim3(16, 16, NH), 256>>>(mask);
    k_softmax<<<NH * NTOK, 256>>>();
    k_pv<<<dim3(1, 16, NH), 256>>>();
    k_out<<<dim3(12, 16), 256>>>(wo, bo, out);
}

// round 2
// speedup vs baseline: 1.0670x; 1.0670x over previous
#include <cuda_runtime.h>
#include <cstdint>

typedef unsigned long long ULL;

#define NTOK 1024
#define CQ   768
#define CZ   128
#define NH   16
#define HD   48
#define HDQ  768   // NH*HD
#define QSCALE 0.14433756729740643f  // 1/sqrt(48)

// ---------------- f32x2 packed helpers ----------------
__device__ __forceinline__ ULL fma2(ULL a, ULL b, ULL c) {
    ULL d; asm("fma.rn.f32x2 %0, %1, %2, %3;" : "=l"(d) : "l"(a), "l"(b), "l"(c)); return d;
}
__device__ __forceinline__ ULL add2(ULL a, ULL b) {
    ULL d; asm("add.rn.f32x2 %0, %1, %2;" : "=l"(d) : "l"(a), "l"(b)); return d;
}
__device__ __forceinline__ ULL pack2(float lo, float hi) {
    ULL d; asm("mov.b64 %0, {%1, %2};" : "=l"(d) : "f"(lo), "f"(hi)); return d;
}
__device__ __forceinline__ float lo2(ULL u){ return __uint_as_float((unsigned)u); }
__device__ __forceinline__ float hi2(ULL u){ return __uint_as_float((unsigned)(u >> 32)); }

// ---------------- scratch (static device globals; no allocation) ----------------
__device__ float g_an[NTOK * CQ];                       // LN(a)
__device__ float g_bias[(size_t)NH * NTOK * NTOK];      // pair bias [h][i][j]
__device__ float g_q[NH * NTOK * HD];                   // [h][n][d] (pre-scaled)
__device__ float g_kT[NH * HD * NTOK];                  // [h][d][n]
__device__ float g_v[NH * NTOK * HD];                   // [h][n][d]
__device__ float g_gate[NTOK * HDQ];                    // sigmoid(an@w_g + b_g)
__device__ float g_og[NTOK * HDQ];                      // gated attention output

// ---------------- LayerNorm of a ----------------
__global__ void k_ln_a(const float* __restrict__ a, const float* __restrict__ g,
                       const float* __restrict__ b) {
    int row = blockIdx.x, tid = threadIdx.x;
    const float* x = a + (size_t)row * CQ;
    float v0 = x[tid], v1 = x[tid + 256], v2 = x[tid + 512];
    float s = v0 + v1 + v2;
    float ss = v0*v0 + v1*v1 + v2*v2;
    __shared__ float sm[8], sm2[8];
    #pragma unroll
    for (int o = 16; o; o >>= 1) {
        s  += __shfl_xor_sync(0xffffffffu, s, o);
        ss += __shfl_xor_sync(0xffffffffu, ss, o);
    }
    if ((tid & 31) == 0) { sm[tid >> 5] = s; sm2[tid >> 5] = ss; }
    __syncthreads();
    if (tid == 0) {
        float S = 0, SS = 0;
        for (int i = 0; i < 8; i++) { S += sm[i]; SS += sm2[i]; }
        float mu = S * (1.0f / CQ);
        float var = SS * (1.0f / CQ) - mu * mu;
        sm[0] = mu; sm2[0] = rsqrtf(var + 1e-5f);
    }
    __syncthreads();
    float mu = sm[0], rstd = sm2[0];
    float* o = g_an + (size_t)row * CQ;
    o[tid]       = (v0 - mu) * rstd * g[tid]       + b[tid];
    o[tid + 256] = (v1 - mu) * rstd * g[tid + 256] + b[tid + 256];
    o[tid + 512] = (v2 - mu) * rstd * g[tid + 512] + b[tid + 512];
}

// ---------------- pair bias v2: LN(z)@w_z fused, 256 rows/block, double-buffered ----------------
#define PB_SMEM_FLOATS (2*256*32 + 2048 + 32)
__global__ __launch_bounds__(256, 2)
void k_pair_bias(const float* __restrict__ z, const float* __restrict__ gz,
                 const float* __restrict__ bz, const float* __restrict__ wz) {
    extern __shared__ float sm[];
    float* zb    = sm;               // 2 x [256][32], rotated f4 layout
    float* wps   = sm + 16384;       // [(c>>1)*32 + h*2 + (c&1)]
    float* cs_cb = wps + 2048;       // colsum[16], cb[16]

    int tid = threadIdx.x;

    for (int i = tid; i < CZ * NH; i += 256) {
        int c = i >> 4, h = i & 15;
        wps[(c >> 1) * 32 + h * 2 + (c & 1)] = gz[c] * wz[c * NH + h];
    }
    __syncthreads();
    if (tid < 16) {
        float cs = 0.f, cb = 0.f;
        for (int c = 0; c < CZ; c++) {
            cs += wps[(c >> 1) * 32 + tid * 2 + (c & 1)];
            cb += bz[c] * wz[c * NH + tid];
        }
        cs_cb[tid] = cs; cs_cb[16 + tid] = cb;
    }
    __syncthreads();

    int tile = blockIdx.x;                         // 4096 tiles x 256 rows
    const float4* zg = (const float4*)(z + (size_t)tile * 256 * CZ);

    // per-thread staging geometry (constant)
    int srow[8], sf[8];
    #pragma unroll
    for (int j = 0; j < 8; j++) { int i = tid + j * 256; srow[j] = i >> 3; sf[j] = i & 7; }

    // prefetch chunk 0
    float4 pre[8];
    #pragma unroll
    for (int j = 0; j < 8; j++)
        pre[j] = zg[(size_t)srow[j] * 32 + sf[j]];

    ULL acc[NH];
    #pragma unroll
    for (int h = 0; h < NH; h++) acc[h] = 0ULL;
    ULL sum2 = 0ULL, ss2 = 0ULL;

    for (int c = 0; c < 4; c++) {
        float* buf = zb + (c & 1) * 8192;
        #pragma unroll
        for (int j = 0; j < 8; j++)
            *(float4*)(buf + srow[j] * 32 + ((sf[j] + srow[j]) & 7) * 4) = pre[j];
        __syncthreads();
        if (c < 3) {
            #pragma unroll
            for (int j = 0; j < 8; j++)
                pre[j] = zg[(size_t)srow[j] * 32 + (c + 1) * 8 + sf[j]];
        }
        #pragma unroll
        for (int j = 0; j < 8; j++) {
            int pos = (j + tid) & 7;
            float4 zv = *(const float4*)(buf + tid * 32 + pos * 4);
            ULL z01 = ((const ULL*)&zv)[0];
            ULL z23 = ((const ULL*)&zv)[1];
            sum2 = add2(sum2, add2(z01, z23));
            ss2  = fma2(z01, z01, fma2(z23, z23, ss2));
            int p0 = c * 16 + 2 * j;
            const float4* w0 = (const float4*)(wps + p0 * 32);
            const float4* w1 = (const float4*)(wps + p0 * 32 + 32);
            #pragma unroll
            for (int h2 = 0; h2 < 8; h2++) {
                float4 wa = w0[h2];
                float4 wb = w1[h2];
                acc[2*h2]     = fma2(z01, ((const ULL*)&wa)[0], acc[2*h2]);
                acc[2*h2 + 1] = fma2(z01, ((const ULL*)&wa)[1], acc[2*h2 + 1]);
                acc[2*h2]     = fma2(z23, ((const ULL*)&wb)[0], acc[2*h2]);
                acc[2*h2 + 1] = fma2(z23, ((const ULL*)&wb)[1], acc[2*h2 + 1]);
            }
        }
        __syncthreads();
    }

    float sum = lo2(sum2) + hi2(sum2);
    float ss  = lo2(ss2)  + hi2(ss2);
    float mu  = sum * (1.0f / CZ);
    float var = ss * (1.0f / CZ) - mu * mu;
    float rstd = rsqrtf(var + 1e-5f);

    float* outs = zb;   // reuse buffer 0 region [16][256]
    #pragma unroll
    for (int h = 0; h < NH; h++) {
        float d = lo2(acc[h]) + hi2(acc[h]);
        outs[h * 256 + tid] = rstd * (d - mu * cs_cb[h]) + cs_cb[16 + h];
    }
    __syncthreads();
    #pragma unroll
    for (int it = 0; it < 4; it++) {
        int idx = tid + it * 256;            // f4 index over 16*64
        int h = idx >> 6, j4 = idx & 63;
        float4 v = *(const float4*)(outs + h * 256 + j4 * 4);
        *(float4*)(g_bias + ((size_t)h << 20) + (size_t)tile * 256 + j4 * 4) = v;
    }
}

// ---------------- generic SGEMM core (kept from R1 for qkvg / out) ----------------
__device__ __forceinline__ void sgemm_core(
    const float* __restrict__ A, const float* __restrict__ B,
    int K, int ldA, int ldB, int Nvalid,
    int row0, int col0, float* sA, float* sB, ULL acc[4][2])
{
    int tid = threadIdx.x;
    int tm = (tid >> 4) << 2;
    int tn = (tid & 15) << 2;
    int ar = tid >> 2,  ak = (tid & 3) << 2;
    int bk = tid >> 4,  bn = (tid & 15) << 2;
    #pragma unroll
    for (int i = 0; i < 4; i++) { acc[i][0] = 0ULL; acc[i][1] = 0ULL; }

    for (int k0 = 0; k0 < K; k0 += 16) {
        float4 av = *(const float4*)(A + (size_t)(row0 + ar) * ldA + (k0 + ak));
        float4 bv = make_float4(0.f, 0.f, 0.f, 0.f);
        if (col0 + bn < Nvalid)
            bv = *(const float4*)(B + (size_t)(k0 + bk) * ldB + (col0 + bn));
        *(float4*)(sA + ar * 20 + ak) = av;
        *(float4*)(sB + bk * 64 + bn) = bv;
        __syncthreads();
        #pragma unroll
        for (int kk = 0; kk < 16; kk++) {
            float4 b4 = *(const float4*)(sB + kk * 64 + tn);
            ULL b01 = ((const ULL*)&b4)[0];
            ULL b23 = ((const ULL*)&b4)[1];
            #pragma unroll
            for (int i = 0; i < 4; i++) {
                float a = sA[(tm + i) * 20 + kk];
                ULL a2 = pack2(a, a);
                acc[i][0] = fma2(a2, b01, acc[i][0]);
                acc[i][1] = fma2(a2, b23, acc[i][1]);
            }
        }
        __syncthreads();
    }
}

// ---------------- QKVG projections ----------------
__global__ void k_qkvg(const float* __restrict__ wq, const float* __restrict__ wk,
                       const float* __restrict__ wv, const float* __restrict__ wg,
                       const float* __restrict__ bg) {
    __shared__ float sA[64 * 20], sB[16 * 64];
    ULL acc[4][2];
    int mode = blockIdx.z;
    const float* B = (mode == 0) ? wq : (mode == 1) ? wk : (mode == 2) ? wv : wg;
    int row0 = blockIdx.y * 64, col0 = blockIdx.x * 64;
    sgemm_core(g_an, B, CQ, CQ, HDQ, HDQ, row0, col0, sA, sB, acc);

    int tid = threadIdx.x;
    int tm = (tid >> 4) << 2, tn = (tid & 15) << 2;
    #pragma unroll
    for (int i = 0; i < 4; i++) {
        int row = row0 + tm + i;
        #pragma unroll
        for (int j = 0; j < 4; j++) {
            int col = col0 + tn + j;
            float v = (j & 1) ? hi2(acc[i][j >> 1]) : lo2(acc[i][j >> 1]);
            int h = col / HD, d = col - h * HD;
            if (mode == 0)      g_q [((size_t)h * NTOK + row) * HD + d] = v * QSCALE;
            else if (mode == 1) g_kT[((size_t)h * HD + d) * NTOK + row] = v;
            else if (mode == 2) g_v [((size_t)h * NTOK + row) * HD + d] = v;
            else                g_gate[(size_t)row * HDQ + col] = 1.f / (1.f + __expf(-(v + bg[col])));
        }
    }
}

// ---------------- fused attention: S=QK^T+bias+mask -> softmax -> PV -> gate ----------------
#define SSTR  1028
#define KTSTR 260
#define VTSTR 52
#define PSTR  1540
#define AT_SMEM_FLOATS (32*SSTR + 12480 + 3072 + 64)

__global__ __launch_bounds__(256, 1)
void k_attn(const float* __restrict__ mask) {
    extern __shared__ float sm[];
    float* S   = sm;                         // [32][1028]
    float* KV  = sm + 32 * SSTR;             // 12480 floats: KtT / Vt x2 / partials
    ULL*   sQd = (ULL*)(sm + 32 * SSTR + 12480);   // [32][48] dup'd Q
    float* sl  = sm + 32 * SSTR + 12480 + 3072;    // 1/rowsum [32]
    float* smr = sl + 32;                    // row mask [32]

    int h = blockIdx.y, qt = blockIdx.x;
    int tid = threadIdx.x;
    int row0 = qt * 32;

    // ---- load Q (dup-packed) + row mask ----
    const float* Q = g_q + ((size_t)h * NTOK + row0) * HD;
    for (int i = tid; i < 32 * HD; i += 256) {
        float v = Q[i];
        sQd[i] = pack2(v, v);
    }
    if (tid < 32) smr[tid] = mask[row0 + tid];
    __syncthreads();

    // ---- phase 1: S = Q*K^T + bias + maskbias over 4 col-chunks of 256 ----
    {
        int kg = tid & 31, qg = tid >> 5;
        const float* biasBase = g_bias + ((size_t)h << 20);
        for (int cc = 0; cc < 4; cc++) {
            int c0 = cc * 256;
            for (int i = tid; i < 48 * 64; i += 256) {
                int d = i >> 6, f = i & 63;
                float4 v = *(const float4*)(g_kT + ((size_t)h * HD + d) * NTOK + c0 + f * 4);
                *(float4*)(KV + d * KTSTR + f * 4) = v;
            }
            __syncthreads();
            ULL acc[4][4];
            #pragma unroll
            for (int i = 0; i < 4; i++)
                #pragma unroll
                for (int j = 0; j < 4; j++) acc[i][j] = 0ULL;
            const ULL* qrow = sQd + (qg * 4) * HD;
            #pragma unroll 8
            for (int kk = 0; kk < HD; kk++) {
                ULL a0 = qrow[kk], a1 = qrow[HD + kk], a2 = qrow[2*HD + kk], a3 = qrow[3*HD + kk];
                const float4* bp = (const float4*)(KV + kk * KTSTR + kg * 8);
                float4 b0 = bp[0], b1 = bp[1];
                ULL bl0 = ((const ULL*)&b0)[0], bh0 = ((const ULL*)&b0)[1];
                ULL bl1 = ((const ULL*)&b1)[0], bh1 = ((const ULL*)&b1)[1];
                acc[0][0] = fma2(a0, bl0, acc[0][0]); acc[0][1] = fma2(a0, bh0, acc[0][1]);
                acc[0][2] = fma2(a0, bl1, acc[0][2]); acc[0][3] = fma2(a0, bh1, acc[0][3]);
                acc[1][0] = fma2(a1, bl0, acc[1][0]); acc[1][1] = fma2(a1, bh0, acc[1][1]);
                acc[1][2] = fma2(a1, bl1, acc[1][2]); acc[1][3] = fma2(a1, bh1, acc[1][3]);
                acc[2][0] = fma2(a2, bl0, acc[2][0]); acc[2][1] = fma2(a2, bh0, acc[2][1]);
                acc[2][2] = fma2(a2, bl1, acc[2][2]); acc[2][3] = fma2(a2, bh1, acc[2][3]);
                acc[3][0] = fma2(a3, bl0, acc[3][0]); acc[3][1] = fma2(a3, bh0, acc[3][1]);
                acc[3][2] = fma2(a3, bl1, acc[3][2]); acc[3][3] = fma2(a3, bh1, acc[3][3]);
            }
            int colb = c0 + kg * 8;
            float4 mc0 = *(const float4*)(mask + colb);
            float4 mc1 = *(const float4*)(mask + colb + 4);
            #pragma unroll
            for (int i = 0; i < 4; i++) {
                int r = qg * 4 + i;
                const float4* bb = (const float4*)(biasBase + (size_t)(row0 + r) * NTOK + colb);
                float4 bv0 = bb[0], bv1 = bb[1];
                float mr = smr[r];
                float4 o0, o1;
                o0.x = lo2(acc[i][0]) + bv0.x + 1e9f * (mr * mc0.x - 1.f);
                o0.y = hi2(acc[i][0]) + bv0.y + 1e9f * (mr * mc0.y - 1.f);
                o0.z = lo2(acc[i][1]) + bv0.z + 1e9f * (mr * mc0.z - 1.f);
                o0.w = hi2(acc[i][1]) + bv0.w + 1e9f * (mr * mc0.w - 1.f);
                o1.x = lo2(acc[i][2]) + bv1.x + 1e9f * (mr * mc1.x - 1.f);
                o1.y = hi2(acc[i][2]) + bv1.y + 1e9f * (mr * mc1.y - 1.f);
                o1.z = lo2(acc[i][3]) + bv1.z + 1e9f * (mr * mc1.z - 1.f);
                o1.w = hi2(acc[i][3]) + bv1.w + 1e9f * (mr * mc1.w - 1.f);
                *(float4*)(S + r * SSTR + colb)     = o0;
                *(float4*)(S + r * SSTR + colb + 4) = o1;
            }
            __syncthreads();
        }
    }

    // ---- phase 2: softmax (exp kept unnormalized; 1/sum saved) ----
    {
        int w = tid >> 5, lane = tid & 31;
        for (int r = w * 4; r < w * 4 + 4; r++) {
            float* Sr = S + r * SSTR;
            float m = -1e30f;
            #pragma unroll
            for (int i = 0; i < 8; i++) {
                float4 v = *(const float4*)(Sr + lane * 4 + i * 128);
                m = fmaxf(m, fmaxf(fmaxf(v.x, v.y), fmaxf(v.z, v.w)));
            }
            #pragma unroll
            for (int o = 16; o; o >>= 1) m = fmaxf(m, __shfl_xor_sync(0xffffffffu, m, o));
            float sum = 0.f;
            #pragma unroll
            for (int i = 0; i < 8; i++) {
                float4 v = *(float4*)(Sr + lane * 4 + i * 128);
                v.x = __expf(v.x - m); v.y = __expf(v.y - m);
                v.z = __expf(v.z - m); v.w = __expf(v.w - m);
                sum += v.x + v.y + v.z + v.w;
                *(float4*)(Sr + lane * 4 + i * 128) = v;
            }
            #pragma unroll
            for (int o = 16; o; o >>= 1) sum += __shfl_xor_sync(0xffffffffu, sum, o);
            if (lane == 0) sl[r] = 1.f / sum;
        }
        __syncthreads();
    }

    // ---- phase 3: O = P*V (k-sliced, f32x2 d-pairs), double-buffered V tiles ----
    {
        int ks = tid & 7, dg = (tid >> 3) & 3, qg = tid >> 5;
        // staging geometry (3 f4 per thread per tile)
        int vr[3], vf[3];
        #pragma unroll
        for (int j = 0; j < 3; j++) { int i = tid + j * 256; vr[j] = i / 12; vf[j] = i - vr[j] * 12; }

        ULL pacc[4][6];
        #pragma unroll
        for (int i = 0; i < 4; i++)
            #pragma unroll
            for (int j = 0; j < 6; j++) pacc[i][j] = 0ULL;

        const float* Vh = g_v + (size_t)h * NTOK * HD;
        float4 pre[3];
        #pragma unroll
        for (int j = 0; j < 3; j++)
            pre[j] = *(const float4*)(Vh + (size_t)vr[j] * HD + vf[j] * 4);

        for (int t = 0; t < 16; t++) {
            float* Vt = KV + (t & 1) * (64 * VTSTR);
            #pragma unroll
            for (int j = 0; j < 3; j++)
                *(float4*)(Vt + vr[j] * VTSTR + vf[j] * 4) = pre[j];
            __syncthreads();
            if (t < 15) {
                #pragma unroll
                for (int j = 0; j < 3; j++)
                    pre[j] = *(const float4*)(Vh + (size_t)((t + 1) * 64 + vr[j]) * HD + vf[j] * 4);
            }
            #pragma unroll
            for (int ii = 0; ii < 8; ii++) {
                int krow = ks + 8 * ii;
                int col = t * 64 + krow;
                float s0 = S[(qg * 4 + 0) * SSTR + col];
                float s1 = S[(qg * 4 + 1) * SSTR + col];
                float s2 = S[(qg * 4 + 2) * SSTR + col];
                float s3 = S[(qg * 4 + 3) * SSTR + col];
                ULL a0 = pack2(s0, s0), a1 = pack2(s1, s1), a2 = pack2(s2, s2), a3 = pack2(s3, s3);
                const float4* vp = (const float4*)(Vt + krow * VTSTR + dg * 12);
                float4 v0 = vp[0], v1 = vp[1], v2 = vp[2];
                ULL b0 = ((const ULL*)&v0)[0], b1 = ((const ULL*)&v0)[1];
                ULL b2 = ((const ULL*)&v1)[0], b3 = ((const ULL*)&v1)[1];
                ULL b4 = ((const ULL*)&v2)[0], b5 = ((const ULL*)&v2)[1];
                pacc[0][0] = fma2(a0, b0, pacc[0][0]); pacc[0][1] = fma2(a0, b1, pacc[0][1]);
                pacc[0][2] = fma2(a0, b2, pacc[0][2]); pacc[0][3] = fma2(a0, b3, pacc[0][3]);
                pacc[0][4] = fma2(a0, b4, pacc[0][4]); pacc[0][5] = fma2(a0, b5, pacc[0][5]);
                pacc[1][0] = fma2(a1, b0, pacc[1][0]); pacc[1][1] = fma2(a1, b1, pacc[1][1]);
                pacc[1][2] = fma2(a1, b2, pacc[1][2]); pacc[1][3] = fma2(a1, b3, pacc[1][3]);
                pacc[1][4] = fma2(a1, b4, pacc[1][4]); pacc[1][5] = fma2(a1, b5, pacc[1][5]);
                pacc[2][0] = fma2(a2, b0, pacc[2][0]); pacc[2][1] = fma2(a2, b1, pacc[2][1]);
                pacc[2][2] = fma2(a2, b2, pacc[2][2]); pacc[2][3] = fma2(a2, b3, pacc[2][3]);
                pacc[2][4] = fma2(a2, b4, pacc[2][4]); pacc[2][5] = fma2(a2, b5, pacc[2][5]);
                pacc[3][0] = fma2(a3, b0, pacc[3][0]); pacc[3][1] = fma2(a3, b1, pacc[3][1]);
                pacc[3][2] = fma2(a3, b2, pacc[3][2]); pacc[3][3] = fma2(a3, b3, pacc[3][3]);
                pacc[3][4] = fma2(a3, b4, pacc[3][4]); pacc[3][5] = fma2(a3, b5, pacc[3][5]);
            }
            __syncthreads();
        }

        // write per-ks partials (d-pair float2s), reduce, gate, store
        float* part = KV;  // [8][32*48 + 4]
        #pragma unroll
        for (int i = 0; i < 4; i++) {
            #pragma unroll
            for (int j = 0; j < 6; j++) {
                int off = ks * PSTR + (qg * 4 + i) * HD + dg * 12 + j * 2;
                *(ULL*)(part + off) = pacc[i][j];
            }
        }
        __syncthreads();
        for (int o = tid; o < 32 * HD; o += 256) {
            float v = 0.f;
            #pragma unroll
            for (int k2 = 0; k2 < 8; k2++) v += part[k2 * PSTR + o];
            int q = o / HD, d = o - q * HD;
            int grow = row0 + q;
            size_t idx = (size_t)grow * HDQ + h * HD + d;
            g_og[idx] = v * sl[q] * g_gate[idx];
        }
    }
}

// ---------------- final projection ----------------
__global__ void k_out(const float* __restrict__ wo, const float* __restrict__ bo,
                      float* __restrict__ out) {
    __shared__ float sA[64 * 20], sB[16 * 64];
    ULL acc[4][2];
    int row0 = blockIdx.y * 64, col0 = blockIdx.x * 64;
    sgemm_core(g_og, wo, CQ, CQ, CQ, CQ, row0, col0, sA, sB, acc);

    int tid = threadIdx.x;
    int tm = (tid >> 4) << 2, tn = (tid & 15) << 2;
    float4 bv = *(const float4*)(bo + col0 + tn);
    #pragma unroll
    for (int i = 0; i < 4; i++) {
        int row = row0 + tm + i;
        float4 r;
        r.x = lo2(acc[i][0]) + bv.x;
        r.y = hi2(acc[i][0]) + bv.y;
        r.z = lo2(acc[i][1]) + bv.z;
        r.w = hi2(acc[i][1]) + bv.w;
        *(float4*)(out + (size_t)row * CQ + col0 + tn) = r;
    }
}

// ---------------- launch ----------------
extern "C" void kernel_launch(void* const* d_in, const int* in_sizes, int n_in,
                              void* d_out, int out_size) {
    const float* a    = (const float*)d_in[0];
    const float* z    = (const float*)d_in[1];
    const float* mask = (const float*)d_in[2];
    const float* ga   = (const float*)d_in[3];
    const float* ba   = (const float*)d_in[4];
    const float* gz   = (const float*)d_in[5];
    const float* bz   = (const float*)d_in[6];
    const float* wz   = (const float*)d_in[7];
    const float* wq   = (const float*)d_in[8];
    const float* wk   = (const float*)d_in[9];
    const float* wv   = (const float*)d_in[10];
    const float* wg   = (const float*)d_in[11];
    const float* bg   = (const float*)d_in[12];
    const float* wo   = (const float*)d_in[13];
    const float* bo   = (const float*)d_in[14];
    float* out = (float*)d_out;

    cudaFuncSetAttribute(k_pair_bias, cudaFuncAttributeMaxDynamicSharedMemorySize,
                         PB_SMEM_FLOATS * 4);
    cudaFuncSetAttribute(k_attn, cudaFuncAttributeMaxDynamicSharedMemorySize,
                         AT_SMEM_FLOATS * 4);

    k_pair_bias<<<4096, 256, PB_SMEM_FLOATS * 4>>>(z, gz, bz, wz);
    k_ln_a<<<1024, 256>>>(a, ga, ba);
    k_qkvg<<<dim3(12, 16, 4), 256>>>(wq, wk, wv, wg, bg);
    k_attn<<<dim3(32, 16), 256, AT_SMEM_FLOATS * 4>>>(mask);
    k_out<<<dim3(12, 16), 256>>>(wo, bo, out);
}